// round 17
// baseline (speedup 1.0000x reference)
#include <cuda_runtime.h>
#include <cuda_bf16.h>

#define FULLMASK 0xffffffffu
typedef unsigned long long u64;

// Qubit -> amplitude-index-bit mapping (layout A):
//   q3->bit0, q5->bit1, q7->bit2  (register bits: j index 0..7)
//   q0->L0, q1->L1, q2->L2, q4->L3, q6->L4  (lane bits)
// amp index = (lane << 3) | j ; amplitude = packed (re, im) in one u64.

__device__ __forceinline__ u64 pk(float lo, float hi) {
    u64 r; asm("mov.b64 %0, {%1, %2};" : "=l"(r) : "f"(lo), "f"(hi)); return r;
}
__device__ __forceinline__ void upk(u64 v, float& x, float& y) {
    asm("mov.b64 {%0, %1}, %2;" : "=f"(x), "=f"(y) : "l"(v));
}
__device__ __forceinline__ u64 f2mul(u64 a, u64 b) {
    u64 r; asm("mul.rn.f32x2 %0, %1, %2;" : "=l"(r) : "l"(a), "l"(b)); return r;
}
__device__ __forceinline__ u64 f2fma(u64 a, u64 b, u64 c) {
    u64 r; asm("fma.rn.f32x2 %0, %1, %2, %3;" : "=l"(r) : "l"(a), "l"(b), "l"(c)); return r;
}
__device__ __forceinline__ u64 f2add(u64 a, u64 b) {
    u64 r; asm("add.rn.f32x2 %0, %1, %2;" : "=l"(r) : "l"(a), "l"(b)); return r;
}
__device__ __forceinline__ u64 swp(u64 v) { float x, y; upk(v, x, y); return pk(y, x); }
__device__ __forceinline__ u64 shx64(u64 v, int m) { return __shfl_xor_sync(FULLMASK, v, m); }
__device__ __forceinline__ u64 shxswp(u64 v, int m) {
    float x, y; upk(v, x, y);
    float sx = __shfl_xor_sync(FULLMASK, x, m);
    float sy = __shfl_xor_sync(FULLMASK, y, m);
    return pk(sy, sx);
}

// ---- Ry on index-bit Tb ----
template <int Tb>
__device__ __forceinline__ void applyRy(u64 s[8], u64 cc, u64 pp, u64 nn, int lane) {
    if constexpr (Tb < 3) {
        constexpr int m = 1 << Tb;
#pragma unroll
        for (int j = 0; j < 8; j++) {
            if (!(j & m)) {
                u64 a = s[j], b = s[j | m];
                s[j]     = f2fma(cc, a, f2mul(nn, b));
                s[j | m] = f2fma(cc, b, f2mul(pp, a));
            }
        }
    } else {
        constexpr int lb = 1 << (Tb - 3);
        u64 sg = (lane & lb) ? pp : nn;
#pragma unroll
        for (int j = 0; j < 8; j++) {
            u64 o = shx64(s[j], lb);
            s[j] = f2fma(cc, s[j], f2mul(sg, o));
        }
    }
}

// ---- controlled rotation: K=0 rx, K=1 ry ----
// G[0]=(c,c) G[1]=(s,s) G[2]=(-s,-s) G[3]=(s,-s) G[4]=(-s,s)
template <int K, int Cb, int Tb>
__device__ __forceinline__ void applyCR(u64 s[8], const u64* __restrict__ G, int lane) {
    u64 cc = G[0];
    if constexpr (Tb < 3) {
        constexpr int tm = 1 << Tb;
        bool lc = (Cb >= 3) ? (((lane >> (Cb - 3)) & 1) != 0) : false;
#pragma unroll
        for (int j = 0; j < 8; j++) {
            if (!(j & tm) && (Cb >= 3 || ((j >> Cb) & 1))) {
                u64 a = s[j], b = s[j | tm], na, nb;
                if constexpr (K == 0) {   // rx
                    u64 pm = G[3];
                    na = f2fma(cc, a, f2mul(pm, swp(b)));
                    nb = f2fma(cc, b, f2mul(pm, swp(a)));
                } else {                  // ry
                    na = f2fma(cc, a, f2mul(G[2], b));
                    nb = f2fma(cc, b, f2mul(G[1], a));
                }
                if constexpr (Cb < 3) { s[j] = na; s[j | tm] = nb; }
                else { if (lc) { s[j] = na; s[j | tm] = nb; } }
            }
        }
    } else {
        constexpr int lb = 1 << (Tb - 3);
        u64 sg = (lane & lb) ? G[1] : G[2];
        if constexpr (Cb < 3) {
#pragma unroll
            for (int j = 0; j < 8; j++) {
                if (j & (1 << Cb)) {
                    if constexpr (K == 0) {
                        u64 os = shxswp(s[j], lb);
                        s[j] = f2fma(cc, s[j], f2mul(G[3], os));
                    } else {
                        u64 o = shx64(s[j], lb);
                        s[j] = f2fma(cc, s[j], f2mul(sg, o));
                    }
                }
            }
        } else {
            bool lc = ((lane >> (Cb - 3)) & 1) != 0;
#pragma unroll
            for (int j = 0; j < 8; j++) {
                u64 r;
                if constexpr (K == 0) r = f2fma(cc, s[j], f2mul(G[3], shxswp(s[j], lb)));
                else                  r = f2fma(cc, s[j], f2mul(sg, shx64(s[j], lb)));
                if (lc) s[j] = r;
            }
        }
    }
}

// ---- general u3 gate: uXr=(re,re), uXi=(-im,im) ----
template <int Tb>
__device__ __forceinline__ void applyU3(u64 s[8], const u64* __restrict__ U, int lane) {
    if constexpr (Tb < 3) {
        constexpr int m = 1 << Tb;
#pragma unroll
        for (int j = 0; j < 8; j++) {
            if (!(j & m)) {
                u64 a = s[j], b = s[j | m];
                u64 as = swp(a), bs = swp(b);
                s[j]     = f2fma(U[0], a, f2fma(U[2], b, f2mul(U[3], bs)));
                s[j | m] = f2fma(U[4], a, f2fma(U[5], as, f2fma(U[6], b, f2mul(U[7], bs))));
            }
        }
    } else {
        constexpr int lb = 1 << (Tb - 3);
        bool hi = (lane & lb) != 0;
        u64 Ar = hi ? U[6] : U[0];
        u64 Ai = hi ? U[7] : U[1];
        u64 Br = hi ? U[4] : U[2];
        u64 Bi = hi ? U[5] : U[3];
#pragma unroll
        for (int j = 0; j < 8; j++) {
            float x, y; upk(s[j], x, y);
            float ox = __shfl_xor_sync(FULLMASK, x, lb);
            float oy = __shfl_xor_sync(FULLMASK, y, lb);
            u64 o = pk(ox, oy), os = pk(oy, ox), ss2 = pk(y, x);
            s[j] = f2fma(Ar, s[j], f2fma(Ai, ss2, f2fma(Br, o, f2mul(Bi, os))));
        }
    }
}

// quadratic-form partial over pairs (a, a|bit)
template <int bit>
__device__ __forceinline__ float quadForm(const u64 s[8], float m, float w2r, float w2i) {
    float acc = 0.f;
#pragma unroll
    for (int j = 0; j < 8; j++) {
        if (!(j & bit)) {
            u64 A = s[j], B = s[j | bit];
            u64 qa = f2mul(A, A), qb = f2mul(B, B);
            u64 rr = f2mul(A, B), ii = f2mul(A, swp(B));
            float qax, qay, qbx, qby, rx, ry, ix, iy;
            upk(qa, qax, qay); upk(qb, qbx, qby);
            upk(rr, rx, ry);   upk(ii, ix, iy);
            acc = fmaf(m, (qax + qay) - (qbx + qby), acc);
            acc = fmaf(w2r, rx + ry, acc);
            acc = fmaf(w2i, ix - iy, acc);
        }
    }
    return acc;
}

// z measurement with PAIRS_B folded into coefficients
__device__ __forceinline__ u64 zMeasure(const u64 s[8],
                                        const float* __restrict__ Z3,
                                        const float* __restrict__ Z7,
                                        const float* __restrict__ Zm, int lane) {
    int q1 = (lane >> 1) & 1;
    float m3 = Zm[0], m7 = Zm[1];
    float w3r0 = Z3[(2 * q1 + 0) * 2 + 0], w3i0 = Z3[(2 * q1 + 0) * 2 + 1];
    float w3r1 = Z3[(2 * q1 + 1) * 2 + 0], w3i1 = Z3[(2 * q1 + 1) * 2 + 1];
    float w7r0 = Z7[0], w7i0 = Z7[1], w7r1 = Z7[2], w7i1 = Z7[3];
    float e3l = 0.f, e7l = 0.f;
#pragma unroll
    for (int jj = 0; jj < 4; jj++) {
        int j = jj * 2;
        float wr = (jj & 1) ? w3r1 : w3r0;
        float wi = (jj & 1) ? w3i1 : w3i0;
        u64 A = s[j], B = s[j | 1];
        u64 qa = f2mul(A, A), qb = f2mul(B, B);
        u64 rr = f2mul(A, B), ii = f2mul(A, swp(B));
        float qax, qay, qbx, qby, rx, ry, ix, iy;
        upk(qa, qax, qay); upk(qb, qbx, qby);
        upk(rr, rx, ry);   upk(ii, ix, iy);
        e3l = fmaf(m3, (qax + qay) - (qbx + qby), e3l);
        e3l = fmaf(wr, rx + ry, e3l);
        e3l = fmaf(wi, ix - iy, e3l);
    }
#pragma unroll
    for (int j = 0; j < 4; j++) {
        float wr = ((j >> 1) & 1) ? w7r1 : w7r0;
        float wi = ((j >> 1) & 1) ? w7i1 : w7i0;
        u64 A = s[j], B = s[j | 4];
        u64 qa = f2mul(A, A), qb = f2mul(B, B);
        u64 rr = f2mul(A, B), ii = f2mul(A, swp(B));
        float qax, qay, qbx, qby, rx, ry, ix, iy;
        upk(qa, qax, qay); upk(qb, qbx, qby);
        upk(rr, rx, ry);   upk(ii, ix, iy);
        e7l = fmaf(m7, (qax + qay) - (qbx + qby), e7l);
        e7l = fmaf(wr, rx + ry, e7l);
        e7l = fmaf(wi, ix - iy, e7l);
    }
    return pk(e3l, e7l);
}

// ---- fused x-branch + z-branch (z is fma-heavy, fills x's shuffle stalls) ----
__device__ __forceinline__ void runBranchXZ(
    u64 sx[8], u64 sz[8],
    const u64* __restrict__ CRx, const u64* __restrict__ UMx,
    const float* __restrict__ M6x,
    const u64* __restrict__ ZAa, const u64* __restrict__ ZAb,
    const u64* __restrict__ UMz,
    const float* __restrict__ Z3, const float* __restrict__ Z7,
    const float* __restrict__ Zm,
    int lane, u64& ex, u64& ez)
{
#define CRGX(i, Cb, Tb) applyCR<0, Cb, Tb>(sx, CRx + (i) * 5, lane);
    // x PAIRS_A gate 0 (lane shuffles) ...
    CRGX(0, 3, 4)
    // ... overlapped with z PAIRS_A combined diagonal (LDS + fma only)
#pragma unroll
    for (int j = 0; j < 8; j++) {
        u64 aa = ZAa[j * 32 + lane], bn = ZAb[j * 32 + lane];
        sz[j] = f2fma(aa, sz[j], f2mul(bn, swp(sz[j])));
    }
    CRGX(1, 5, 0)
    applyU3<0>(sz, UMz + 1 * 8, lane);     // z u3(q3) register-local
    CRGX(2, 6, 1)
    applyU3<1>(sz, UMz + 2 * 8, lane);     // z u3(q5) register-local
    CRGX(3, 7, 2)
    applyU3<2>(sz, UMz + 3 * 8, lane);     // z u3(q7) register-local
    CRGX(4, 4, 5)
    CRGX(5, 0, 6)
    CRGX(6, 1, 7)
    applyU3<4>(sz, UMz + 0 * 8, lane);     // z u3(q1) lane-target
    // x u3 layer
    applyU3<4>(sx, UMx + 0 * 8, lane);
    applyU3<0>(sx, UMx + 1 * 8, lane);
    applyU3<1>(sx, UMx + 2 * 8, lane);
    applyU3<2>(sx, UMx + 3 * 8, lane);
    // z measurement (pure fma) overlapped with x PAIRS_B
    ez = zMeasure(sz, Z3, Z7, Zm, lane);
    CRGX(7, 4, 0)
    CRGX(8, 1, 2)
    float e7l = quadForm<4>(sx, M6x[3], M6x[4], M6x[5]);
    CRGX(9, 0, 1)
    float e3l = quadForm<1>(sx, M6x[0], M6x[1], M6x[2]);
    ex = pk(e3l, e7l);
#undef CRGX
}

// ---- y branch (K=1): returns unreduced packed (e3, e7) ----
__device__ __forceinline__ u64 runBranchY(u64 s[8], const u64* __restrict__ CR,
                                          const u64* __restrict__ UM,
                                          const float* __restrict__ M6, int lane) {
#define CRG(i, Cb, Tb) applyCR<1, Cb, Tb>(s, CR + (i) * 5, lane);
#define U3G(i, Tb) applyU3<Tb>(s, UM + (i) * 8, lane);
    CRG(0, 3, 4) CRG(1, 5, 0) CRG(2, 6, 1) CRG(3, 7, 2)
    CRG(4, 4, 5) CRG(5, 0, 6) CRG(6, 1, 7)
    U3G(0, 4) U3G(1, 0) U3G(2, 1) U3G(3, 2)
    CRG(7, 4, 0)
    CRG(8, 1, 2)
    float e7l = quadForm<4>(s, M6[3], M6[4], M6[5]);
    CRG(9, 0, 1)
    float e3l = quadForm<1>(s, M6[0], M6[1], M6[2]);
#undef CRG
#undef U3G
    return pk(e3l, e7l);
}

__global__ __launch_bounds__(256) void qcnn_kernel(
    const float* __restrict__ theta, const float* __restrict__ phi,
    const float* __restrict__ angles_x, const float* __restrict__ angles_y,
    const float* __restrict__ angles_z,
    const float* __restrict__ u3_x, const float* __restrict__ u3_y,
    const float* __restrict__ u3_z,
    const float* __restrict__ W1, const float* __restrict__ b1,
    const float* __restrict__ W2, const float* __restrict__ b2,
    float* __restrict__ out, int B)
{
    __shared__ u64 shCR[2 * 10 * 5];   // x,y rotation consts
    __shared__ u64 shU3[3 * 6 * 8];
    __shared__ u64 shBuf[8 * 576];     // per-warp DOUBLE transpose buffer (+psi0 stash)
    __shared__ u64 shZAa[256], shZAb[256];  // z PAIRS_A diagonal table
    __shared__ float shM[12];          // x,y fold consts
    __shared__ float shZ3[8], shZ7[4], shZm[2];  // z folded measurement consts
    __shared__ float shW1[72], shB1[12], shW2[12];
    __shared__ float shB2;

    int tid = threadIdx.x;
    // z PAIRS_A diagonal table: every thread computes one entry
    {
        int j = tid >> 5, ln = tid & 31;
        float q[8];
        q[0] = (float)(ln & 1);        q[1] = (float)((ln >> 1) & 1);
        q[2] = (float)((ln >> 2) & 1); q[4] = (float)((ln >> 3) & 1);
        q[6] = (float)((ln >> 4) & 1);
        q[3] = (float)(j & 1); q[5] = (float)((j >> 1) & 1); q[7] = (float)((j >> 2) & 1);
        const int pc[7] = {0, 2, 4, 6, 1, 3, 5};
        const int pt[7] = {1, 3, 5, 7, 2, 4, 6};
        float ang = 0.f;
#pragma unroll
        for (int i = 0; i < 7; i++)
            ang += q[pc[i]] * (q[pt[i]] > 0.5f ? 0.5f : -0.5f) * angles_z[i];
        float sn, cs; sincosf(ang, &sn, &cs);
        shZAa[tid] = pk(cs, cs);
        shZAb[tid] = pk(-sn, sn);
    }
    if (tid < 20) {
        int b = tid / 10, i = tid % 10;
        const float* ang = (b == 0) ? angles_x : angles_y;
        float sn, c;
        sincosf(0.5f * ang[i], &sn, &c);
        u64* g = &shCR[tid * 5];
        g[0] = pk(c, c);
        g[1] = pk(sn, sn);
        g[2] = pk(-sn, -sn);
        g[3] = pk(sn, -sn);
        g[4] = pk(-sn, sn);
    }
    if (tid >= 32 && tid < 50) {
        int k = tid - 32;
        int b = k / 6, i = k % 6;
        const float* up = ((b == 0) ? u3_x : (b == 1) ? u3_y : u3_z) + i * 3;
        float th = up[0], ph = up[1], lm = up[2];
        float sn, c;    sincosf(0.5f * th, &sn, &c);
        float sl, cl;   sincosf(lm, &sl, &cl);
        float sp, cp;   sincosf(ph, &sp, &cp);
        float spl, cpl; sincosf(ph + lm, &spl, &cpl);
        u64* g = &shU3[k * 8];
        g[0] = pk(c, c);                 g[1] = pk(0.f, 0.f);
        g[2] = pk(-cl * sn, -cl * sn);   g[3] = pk(sl * sn, -sl * sn);
        g[4] = pk(cp * sn, cp * sn);     g[5] = pk(-sp * sn, sp * sn);
        g[6] = pk(cpl * c, cpl * c);     g[7] = pk(-spl * c, spl * c);
    }
    if (tid >= 50 && tid < 54) {
        // x,y measurement folds: M = u3†Zu3
        int k2 = tid - 50;
        int b = k2 / 2, wire = k2 % 2;
        const float* up = ((b == 0) ? u3_x : u3_y) + (4 + wire) * 3;
        float th = up[0], lm = up[2];
        float st, ct; sincosf(th, &st, &ct);
        float sl, cl; sincosf(lm, &sl, &cl);
        float* m = &shM[b * 6 + wire * 3];
        m[0] = ct;
        m[1] = -2.f * st * cl;
        m[2] =  2.f * st * sl;
    }
    if (tid >= 56 && tid < 60) {
        int v = tid - 56;
        float q1v = (float)((v >> 1) & 1), q5v = (float)(v & 1);
        float del = q1v * angles_z[7] + (q5v > 0.5f ? 0.5f : -0.5f) * angles_z[9];
        float sd, cd; sincosf(del, &sd, &cd);
        float th = u3_z[12], lm = u3_z[14];
        float st, ct; sincosf(th, &st, &ct);
        float sl, cl; sincosf(lm, &sl, &cl);
        float w2r = -2.f * st * cl, w2i = 2.f * st * sl;
        shZ3[v * 2 + 0] = w2r * cd + w2i * sd;
        shZ3[v * 2 + 1] = -w2r * sd + w2i * cd;
        if (v == 0) shZm[0] = ct;
    }
    if (tid >= 60 && tid < 62) {
        int v = tid - 60;
        float del = (float)v * angles_z[8];
        float sd, cd; sincosf(del, &sd, &cd);
        float th = u3_z[15], lm = u3_z[17];
        float st, ct; sincosf(th, &st, &ct);
        float sl, cl; sincosf(lm, &sl, &cl);
        float w2r = -2.f * st * cl, w2i = 2.f * st * sl;
        shZ7[v * 2 + 0] = w2r * cd + w2i * sd;
        shZ7[v * 2 + 1] = -w2r * sd + w2i * cd;
        if (v == 0) shZm[1] = ct;
    }
    if (tid >= 64 && tid < 136)  shW1[tid - 64] = W1[tid - 64];
    if (tid >= 136 && tid < 148) shB1[tid - 136] = b1[tid - 136];
    if (tid >= 148 && tid < 160) shW2[tid - 148] = W2[tid - 148];
    if (tid == 160) shB2 = b2[0];
    __syncthreads();

    int warp = tid >> 5;
    int lane = tid & 31;
    int batch = blockIdx.x * 8 + warp;
    if (batch >= B) return;

    float th = theta[batch];
    float ph = phi[batch];

    float sy, cy;
    sincosf(0.5f * th, &sy, &cy);
    u64 cc = pk(cy, cy), pp = pk(sy, sy), nn = pk(-sy, -sy);

    // Rz-layer diagonal tables
    float c1x, c1y; sincosf(ph, &c1y, &c1x);
    float cl0x, cl0y; sincosf(ph * (float)(__popc(lane) - 4), &cl0y, &cl0x);
    float px[4], py[4];
    px[0] = cl0x; py[0] = cl0y;
    px[1] = px[0] * c1x - py[0] * c1y; py[1] = px[0] * c1y + py[0] * c1x;
    px[2] = px[1] * c1x - py[1] * c1y; py[2] = px[1] * c1y + py[1] * c1x;
    px[3] = px[2] * c1x - py[2] * c1y; py[3] = px[2] * c1y + py[2] * c1x;
    const int POPC[8] = {0, 1, 1, 2, 1, 2, 2, 3};

    // ---- transpose addressing ----
    u64* buf0 = &shBuf[warp * 576];
    u64* buf1 = buf0 + 288;
    int low3 = lane & 7, hi2 = (lane >> 3) & 3;
    u64* baseA0 = buf0 + low3 + 72 * hi2;
    u64* baseB0 = buf0 + 9 * low3 + 72 * hi2;
    u64* baseB1 = buf1 + 9 * low3 + 72 * hi2;
    int l0 = lane & 1, l1 = (lane >> 1) & 1, l2 = (lane >> 2) & 1;
    int l3 = (lane >> 3) & 1, l4 = (lane >> 4) & 1;
    int adrR[8];
#pragma unroll
    for (int j = 0; j < 8; j++) {
        int j0 = j & 1, j1 = (j >> 1) & 1, j2 = (j >> 2) & 1;
        int x0 = l0 ^ j2, x1 = l1 ^ l0 ^ j2, x2 = l2 ^ l1;
        int x3 = j0 ^ l2, x4 = l3 ^ j0, x5 = j1 ^ l3, x6 = l4 ^ j1, x7 = l4 ^ j2;
        adrR[j] = (x0 + 2 * x1 + 4 * x2) + 9 * (x3 + 2 * x5 + 4 * x7) + 72 * (x4 + 2 * x6);
    }

    // ---- cycle 1: closed-form product state with ring folded ----
    u64 s[8];
    {
        float tn = sy / cy;
        float zr = tn * c1x, zi = tn * c1y;
        float cy2 = cy * cy, cy4 = cy2 * cy2, cy8 = cy4 * cy4;
        float c2r = c1x * c1x - c1y * c1y, c2i = 2.f * c1x * c1y;
        float c4r = c2r * c2r - c2i * c2i, c4i = 2.f * c2r * c2i;
        float tr = cy8 * c4r, ti = -cy8 * c4i;
        u64 myT = 0;
#pragma unroll
        for (int p = 0; p < 9; p++) {
            if (lane == p) myT = pk(tr, ti);
            float nr = tr * zr - ti * zi;
            ti = tr * zi + ti * zr;
            tr = nr;
        }
        if (lane < 9) buf0[lane] = myT;
        __syncwarp();
        int lb = l0 | ((l1 ^ l0) << 1) | ((l2 ^ l1) << 2) | (l2 << 3) | (l3 * 48) | (l4 * 192);
        const int JB[8] = {0, 24, 96, 120, 131, 155, 227, 251};
#pragma unroll
        for (int j = 0; j < 8; j++) s[j] = buf0[__popc(lb ^ JB[j])];
        __syncwarp();
    }

    // ---- cycles 2..4 ----
#pragma unroll 1
    for (int cyc = 0; cyc < 3; cyc++) {
        applyRy<0>(s, cc, pp, nn, lane);
        applyRy<1>(s, cc, pp, nn, lane);
        applyRy<2>(s, cc, pp, nn, lane);
#pragma unroll
        for (int j = 0; j < 8; j++) baseA0[9 * j] = s[j];
        __syncwarp();
#pragma unroll
        for (int j = 0; j < 8; j++) s[j] = baseB0[j];
        applyRy<0>(s, cc, pp, nn, lane);
        applyRy<1>(s, cc, pp, nn, lane);
        applyRy<2>(s, cc, pp, nn, lane);
        applyRy<6>(s, cc, pp, nn, lane);
        applyRy<7>(s, cc, pp, nn, lane);
#pragma unroll
        for (int j = 0; j < 8; j++) {
            float x, y; upk(s[j], x, y);
            int d = POPC[j];
            s[j] = pk(px[d] * x - py[d] * y, px[d] * y + py[d] * x);
        }
#pragma unroll
        for (int j = 0; j < 8; j++) baseB1[j] = s[j];
        __syncwarp();
#pragma unroll
        for (int j = 0; j < 8; j++) s[j] = buf1[adrR[j]];
    }

    // ---- stash psi0 in smem for the y branch (same-lane slots, no sync) ----
#pragma unroll
    for (int j = 0; j < 8; j++) buf0[j * 32 + lane] = s[j];

    // z working copy from registers
    u64 sz[8];
#pragma unroll
    for (int j = 0; j < 8; j++) sz[j] = s[j];

    // fused x + z branches (z fills x's shuffle-latency bubbles)
    u64 ex, ez;
    runBranchXZ(s, sz, &shCR[0], &shU3[0], &shM[0],
                shZAa, shZAb, &shU3[96], shZ3, shZ7, shZm, lane, ex, ez);

    // y branch on reloaded psi0
#pragma unroll
    for (int j = 0; j < 8; j++) s[j] = buf0[j * 32 + lane];
    u64 ey = runBranchY(s, &shCR[50], &shU3[48], &shM[6], lane);

    // batched reductions (3 independent chains)
#pragma unroll
    for (int o = 16; o > 0; o >>= 1) {
        ex = f2add(ex, shx64(ex, o));
        ey = f2add(ey, shx64(ey, o));
        ez = f2add(ez, shx64(ez, o));
    }
    float feats[6];
    upk(ex, feats[0], feats[1]);
    upk(ey, feats[2], feats[3]);
    upk(ez, feats[4], feats[5]);

    // ---- MLP: parallel across lanes 0..11 ----
    {
        float o = 0.f;
        if (lane < 12) {
            float a = shB1[lane];
#pragma unroll
            for (int f = 0; f < 6; f++) a = fmaf(shW1[lane * 6 + f], feats[f], a);
            o = tanhf(a) * shW2[lane];
        }
#pragma unroll
        for (int w = 16; w > 0; w >>= 1) o += __shfl_xor_sync(FULLMASK, o, w);
        if (lane == 0) out[batch] = 1.f / (1.f + expf(-(o + shB2)));
    }
}

extern "C" void kernel_launch(void* const* d_in, const int* in_sizes, int n_in,
                              void* d_out, int out_size) {
    const float* theta    = (const float*)d_in[0];
    const float* phi      = (const float*)d_in[1];
    const float* angles_x = (const float*)d_in[2];
    const float* angles_y = (const float*)d_in[3];
    const float* angles_z = (const float*)d_in[4];
    const float* u3_x     = (const float*)d_in[5];
    const float* u3_y     = (const float*)d_in[6];
    const float* u3_z     = (const float*)d_in[7];
    const float* W1       = (const float*)d_in[8];
    const float* b1       = (const float*)d_in[9];
    const float* W2       = (const float*)d_in[10];
    const float* b2       = (const float*)d_in[11];
    float* out = (float*)d_out;

    int B = in_sizes[0];
    int blocks = (B + 7) / 8;
    qcnn_kernel<<<blocks, 256>>>(theta, phi, angles_x, angles_y, angles_z,
                                 u3_x, u3_y, u3_z, W1, b1, W2, b2, out, B);
}